// round 13
// baseline (speedup 1.0000x reference)
#include <cuda_runtime.h>
#include <cuda_fp16.h>
#include <cstdint>

#define N_NODES 50000
#define E_MAX   850000
#define SCAN_B  1024

// ---------------- scratch (allocation-free: __device__ globals; zero-initialized at load) ----------------
__device__ __align__(128) int    g_cntr[N_NODES];
__device__ __align__(128) int    g_cntc[N_NODES];
__device__ __align__(128) int    g_rp  [N_NODES + 1];
__device__ __align__(128) int    g_fill[N_NODES];
__device__ __align__(128) int    g_bsum[64];
__device__ __align__(128) int    g_srt [E_MAX];
__device__ __align__(128) float  g_dis [N_NODES];
__device__ __align__(128) __half g_xs  [N_NODES * 64];    // fp16 x * dis[row]
__device__ __align__(128) float  g_agg1[N_NODES * 64];
__device__ __align__(128) __half g_h1s [N_NODES * 128];   // fp16 h1 * dis[row]
__device__ __align__(128) float  g_agg2[N_NODES * 128];
__device__ __align__(128) __half g_ABh [N_NODES * 256];   // fp16 [A | B] per node
__device__ __align__(128) float  g_Wf  [128 * 256];       // W2 @ [Wc1_top | Wc1_bot]
__device__ __align__(128) float  g_bf  [256];             // [b2@Wc1_top + bc1 | b2@Wc1_bot]

// ---------------- helpers ----------------
__device__ __forceinline__ uint32_t f2tf32(float f) {
    uint32_t r; asm("cvt.rna.tf32.f32 %0, %1;" : "=r"(r) : "f"(f)); return r;
}
__device__ __forceinline__ void mma_tf32(float* d, const uint32_t* a, uint32_t b0, uint32_t b1) {
    asm volatile(
        "mma.sync.aligned.m16n8k8.row.col.f32.tf32.tf32.f32 "
        "{%0,%1,%2,%3}, {%4,%5,%6,%7}, {%8,%9}, {%0,%1,%2,%3};"
        : "+f"(d[0]), "+f"(d[1]), "+f"(d[2]), "+f"(d[3])
        : "r"(a[0]), "r"(a[1]), "r"(a[2]), "r"(a[3]), "r"(b0), "r"(b1));
}

// ---------------- CSR build ----------------
__global__ void k_count(const int* __restrict__ ei, int E) {
    int e = blockIdx.x * blockDim.x + threadIdx.x;
    if (e >= E) return;
    atomicAdd(&g_cntr[__ldg(ei + e)], 1);
    atomicAdd(&g_cntc[__ldg(ei + E + e)], 1);
}
// phase 1: per-block exclusive scan of cntc; also dis = rsqrt(1+cntr)
__global__ __launch_bounds__(SCAN_B) void k_scan_blk(int n) {
    __shared__ int wsum[32];
    int tid = threadIdx.x, lane = tid & 31, wid = tid >> 5;
    int i = blockIdx.x * SCAN_B + tid;
    if (i < n) g_dis[i] = rsqrtf(1.0f + (float)g_cntr[i]);
    int v = (i < n) ? g_cntc[i] : 0;
    int s = v;
#pragma unroll
    for (int o = 1; o < 32; o <<= 1) {
        int t = __shfl_up_sync(0xffffffffu, s, o);
        if (lane >= o) s += t;
    }
    if (lane == 31) wsum[wid] = s;
    __syncthreads();
    if (wid == 0) {
        int ws = wsum[lane];
#pragma unroll
        for (int o = 1; o < 32; o <<= 1) {
            int t = __shfl_up_sync(0xffffffffu, ws, o);
            if (lane >= o) ws += t;
        }
        wsum[lane] = ws;
    }
    __syncthreads();
    int incl = s + (wid ? wsum[wid - 1] : 0);
    if (i < n) g_rp[i] = incl - v;
    if (tid == SCAN_B - 1) g_bsum[blockIdx.x] = incl;
}
// phase 2+3: block offset from g_bsum + add; ALSO converts x -> xs = fp16(x*dis)
__global__ __launch_bounds__(SCAN_B) void k_scan_add(const float* __restrict__ x, int n, int nblk) {
    __shared__ int red[2];
    int b = blockIdx.x, tid = threadIdx.x;
    if (tid < 64) {
        int v = (tid < b) ? g_bsum[tid] : 0;
#pragma unroll
        for (int o = 16; o > 0; o >>= 1) v += __shfl_down_sync(0xffffffffu, v, o);
        if ((tid & 31) == 0) red[tid >> 5] = v;
    }
    __syncthreads();
    int off = red[0] + red[1];
    int i = b * SCAN_B + tid;
    if (i < n) {
        int v = g_rp[i] + off;
        g_rp[i] = v;
        g_fill[i] = v;
        // convert row i of x, pre-scaled by dis[i]
        float d = g_dis[i];
        const float4* x4 = (const float4*)x;
        uint2* xs2 = (uint2*)g_xs;
#pragma unroll 4
        for (int k = 0; k < 16; k++) {
            float4 v4 = x4[i * 16 + k];
            __half2 a = __floats2half2_rn(v4.x * d, v4.y * d);
            __half2 c = __floats2half2_rn(v4.z * d, v4.w * d);
            uint2 u;
            u.x = *(uint32_t*)&a;
            u.y = *(uint32_t*)&c;
            xs2[i * 16 + k] = u;
        }
    }
    if (b == nblk - 1 && tid == 0) g_rp[n] = off + g_bsum[b];
}
// permute + re-zero cnt arrays for next graph replay (cntr/cntc fully consumed by k_scan_blk)
__global__ void k_permute(const int* __restrict__ ei, int E, int n) {
    int e = blockIdx.x * blockDim.x + threadIdx.x;
    if (e < E) {
        int r = __ldg(ei + e);
        int c = __ldg(ei + E + e);
        int pos = atomicAdd(&g_fill[c], 1);
        g_srt[pos] = r;
    }
    if (e < n) { g_cntr[e] = 0; g_cntc[e] = 0; }
}

// ---------------- gather convs (warp per node; rows pre-scaled, pure-add inner loop) ----------------
// agg1[i] = dis_i * (xs[i] + sum_e xs[src])
__global__ __launch_bounds__(256) void k_gather1(int n) {
    int node = blockIdx.x * 8 + (threadIdx.x >> 5);
    int lane = threadIdx.x & 31;
    if (node >= n) return;
    const __half2* xs2 = (const __half2*)g_xs;
    float2 acc = __half22float2(xs2[node * 32 + lane]);
    int e = g_rp[node], end = g_rp[node + 1];
    while (e < end) {
        int cnt = end - e;
        if (cnt > 32) cnt = 32;
        int idx = (lane < cnt) ? __ldg(g_srt + e + lane) : 0;
#pragma unroll 4
        for (int j = 0; j < cnt; j++) {
            int s = __shfl_sync(0xffffffffu, idx, j);
            float2 v = __half22float2(xs2[s * 32 + lane]);
            acc.x += v.x;
            acc.y += v.y;
        }
        e += cnt;
    }
    float di = g_dis[node];
    acc.x *= di; acc.y *= di;
    ((float2*)g_agg1)[node * 32 + lane] = acc;
}
// agg2[i] = dis_i * (h1s[i] + sum_e h1s[src])
__global__ __launch_bounds__(256) void k_gather2(int n) {
    int node = blockIdx.x * 8 + (threadIdx.x >> 5);
    int lane = threadIdx.x & 31;
    if (node >= n) return;
    const uint2* h2 = (const uint2*)g_h1s;
    uint2 us = h2[node * 32 + lane];
    float2 f0 = __half22float2(*(__half2*)&us.x);
    float2 f1 = __half22float2(*(__half2*)&us.y);
    float4 acc = make_float4(f0.x, f0.y, f1.x, f1.y);
    int e = g_rp[node], end = g_rp[node + 1];
    while (e < end) {
        int cnt = end - e;
        if (cnt > 32) cnt = 32;
        int idx = (lane < cnt) ? __ldg(g_srt + e + lane) : 0;
#pragma unroll 4
        for (int j = 0; j < cnt; j++) {
            int s = __shfl_sync(0xffffffffu, idx, j);
            uint2 u0 = h2[s * 32 + lane];
            float2 a0 = __half22float2(*(__half2*)&u0.x);
            float2 a1 = __half22float2(*(__half2*)&u0.y);
            acc.x += a0.x;
            acc.y += a0.y;
            acc.z += a1.x;
            acc.w += a1.y;
        }
        e += cnt;
    }
    float di = g_dis[node];
    acc.x *= di; acc.y *= di; acc.z *= di; acc.w *= di;
    ((float4*)g_agg2)[node * 32 + lane] = acc;
}

// ---------------- fold prep (weights + bias in one kernel) ----------------
__global__ void k_foldw(const float* __restrict__ W2, const float* __restrict__ Wc1,
                        const float* __restrict__ b2, const float* __restrict__ bc1) {
    if (blockIdx.x == 128) {
        int n = threadIdx.x;
        int which = n >> 7, nn = n & 127;
        const float* wc = Wc1 + (which * 128) * 128 + nn;
        float acc = 0.f;
#pragma unroll 8
        for (int j = 0; j < 128; j++) acc = fmaf(b2[j], __ldg(wc + j * 128), acc);
        g_bf[n] = acc + (which ? 0.f : bc1[nn]);
        return;
    }
    int idx = blockIdx.x * 256 + threadIdx.x;
    int k = idx >> 8, n = idx & 255;
    int which = n >> 7, nn = n & 127;
    const float* w2row = W2 + k * 128;
    const float* wc = Wc1 + (which * 128) * 128 + nn;
    float acc = 0.f;
#pragma unroll 8
    for (int j = 0; j < 128; j++) acc = fmaf(__ldg(w2row + j), __ldg(wc + j * 128), acc);
    g_Wf[idx] = acc;
}

// ---------------- tf32 mma.sync GEMM ----------------
// OUTH: fp16 output. DSCALE: multiply output rows by g_dis[row] (for h1s path).
#define SA 68
template <bool RELU, int OUTH, int DSCALE>
__global__ __launch_bounds__(256) void gemm_mma(
    const float* __restrict__ A, const float* __restrict__ W,
    const float* __restrict__ bias, void* __restrict__ Cv,
    int M, int K, int NC) {
    extern __shared__ uint32_t sm[];
    uint32_t* As = sm;              // 128*68
    uint32_t* Ws = sm + 128 * SA;   // 128*68
    int tid = threadIdx.x, wid = tid >> 5, lane = tid & 31;
    int row0 = blockIdx.x * 128, col0 = blockIdx.y * 128;
    int wm = (wid & 3) * 32, wn = (wid >> 2) * 64;
    int gid = lane >> 2, tig = lane & 3;

    float acc[2][8][4];
#pragma unroll
    for (int ma = 0; ma < 2; ma++)
#pragma unroll
        for (int na = 0; na < 8; na++)
#pragma unroll
            for (int q = 0; q < 4; q++) acc[ma][na][q] = 0.f;

    int lda4 = K >> 2;
    const float4* A4 = (const float4*)A;

    for (int kc = 0; kc < K; kc += 64) {
        for (int i = tid; i < 128 * 16; i += 256) {
            int r = i >> 4, kk = i & 15;
            float4 v = make_float4(0.f, 0.f, 0.f, 0.f);
            int gr = row0 + r;
            if (gr < M) v = A4[gr * lda4 + (kc >> 2) + kk];
            uint4 tv;
            tv.x = f2tf32(v.x); tv.y = f2tf32(v.y); tv.z = f2tf32(v.z); tv.w = f2tf32(v.w);
            *(uint4*)(As + r * SA + kk * 4) = tv;
        }
        for (int i = tid; i < 64 * 128; i += 256) {
            int k = i >> 7, n = i & 127;
            Ws[n * SA + k] = f2tf32(__ldg(W + (kc + k) * NC + col0 + n));
        }
        __syncthreads();

        const uint32_t* a0p = As + (wm + gid) * SA;
        const uint32_t* b0p = Ws + (wn + gid) * SA;
#pragma unroll
        for (int ks = 0; ks < 64; ks += 8) {
            uint32_t afr[2][4];
#pragma unroll
            for (int ma = 0; ma < 2; ma++) {
                const uint32_t* p = a0p + ma * 16 * SA + ks + tig;
                afr[ma][0] = p[0];
                afr[ma][1] = p[8 * SA];
                afr[ma][2] = p[4];
                afr[ma][3] = p[8 * SA + 4];
            }
#pragma unroll
            for (int na = 0; na < 8; na++) {
                const uint32_t* p = b0p + na * 8 * SA + ks + tig;
                uint32_t b0 = p[0], b1 = p[4];
                mma_tf32(acc[0][na], afr[0], b0, b1);
                mma_tf32(acc[1][na], afr[1], b0, b1);
            }
        }
        __syncthreads();
    }

#pragma unroll
    for (int ma = 0; ma < 2; ma++) {
        int r0 = row0 + wm + ma * 16 + gid;
        float d0 = 1.f, d1 = 1.f;
        if (DSCALE) {
            if (r0 < M)     d0 = g_dis[r0];
            if (r0 + 8 < M) d1 = g_dis[r0 + 8];
        }
#pragma unroll
        for (int na = 0; na < 8; na++) {
            int c = col0 + wn + na * 8 + 2 * tig;
            float bx = bias[c], by = bias[c + 1];
            float2 v0, v1;
            v0.x = acc[ma][na][0] + bx; v0.y = acc[ma][na][1] + by;
            v1.x = acc[ma][na][2] + bx; v1.y = acc[ma][na][3] + by;
            if (RELU) {
                v0.x = fmaxf(v0.x, 0.f); v0.y = fmaxf(v0.y, 0.f);
                v1.x = fmaxf(v1.x, 0.f); v1.y = fmaxf(v1.y, 0.f);
            }
            if (DSCALE) {
                v0.x *= d0; v0.y *= d0;
                v1.x *= d1; v1.y *= d1;
            }
            if (OUTH) {
                __half* C = (__half*)Cv;
                if (r0 < M)     *(__half2*)(C + (long)r0 * NC + c)       = __floats2half2_rn(v0.x, v0.y);
                if (r0 + 8 < M) *(__half2*)(C + (long)(r0 + 8) * NC + c) = __floats2half2_rn(v1.x, v1.y);
            } else {
                float* C = (float*)Cv;
                if (r0 < M)     *(float2*)(C + (long)r0 * NC + c)       = v0;
                if (r0 + 8 < M) *(float2*)(C + (long)(r0 + 8) * NC + c) = v1;
            }
        }
    }
}

// ---------------- query (fp16 AB reads) ----------------
__global__ void k_query(const int* __restrict__ eli, const float* __restrict__ Wc2,
                        const float* __restrict__ bc2, float* __restrict__ out, int Q) {
    int t = blockIdx.x * blockDim.x + threadIdx.x;
    int q = t >> 5, lane = t & 31;
    if (q >= Q) return;
    int s = __ldg(eli + q);
    int d = __ldg(eli + Q + q);
    const uint2* AB2 = (const uint2*)g_ABh;    // 4 halves per lane
    uint2 ua = AB2[s * 64 + lane];
    uint2 ub = AB2[d * 64 + 32 + lane];
    float2 a0 = __half22float2(*(__half2*)&ua.x);
    float2 a1 = __half22float2(*(__half2*)&ua.y);
    float2 b0 = __half22float2(*(__half2*)&ub.x);
    float2 b1 = __half22float2(*(__half2*)&ub.y);
    float4 w = ((const float4*)Wc2)[lane];
    float ux = fmaxf(a0.x + b0.x, 0.f);
    float uy = fmaxf(a0.y + b0.y, 0.f);
    float uz = fmaxf(a1.x + b1.x, 0.f);
    float uw = fmaxf(a1.y + b1.y, 0.f);
    float sum = ux * w.x + uy * w.y + uz * w.z + uw * w.w;
#pragma unroll
    for (int o = 16; o > 0; o >>= 1) sum += __shfl_xor_sync(0xffffffffu, sum, o);
    if (lane == 0) out[q] = sum + bc2[0];
}

extern "C" void kernel_launch(void* const* d_in, const int* in_sizes, int n_in,
                              void* d_out, int out_size) {
    const float* x   = (const float*)d_in[0];
    const int*   ei  = (const int*)  d_in[1];
    const int*   eli = (const int*)  d_in[2];
    const float* W1  = (const float*)d_in[3];
    const float* b1  = (const float*)d_in[4];
    const float* W2  = (const float*)d_in[5];
    const float* b2  = (const float*)d_in[6];
    const float* Wc1 = (const float*)d_in[7];
    const float* bc1 = (const float*)d_in[8];
    const float* Wc2 = (const float*)d_in[9];
    const float* bc2 = (const float*)d_in[10];
    float* out = (float*)d_out;

    int N = in_sizes[0] / 64;
    int E = in_sizes[1] / 2;
    int Q = in_sizes[2] / 2;

    float *agg1, *Wfp, *bfp, *agg2;
    __half *h1s, *ABh;
    cudaGetSymbolAddress((void**)&agg1, g_agg1);
    cudaGetSymbolAddress((void**)&h1s,  g_h1s);
    cudaGetSymbolAddress((void**)&ABh,  g_ABh);
    cudaGetSymbolAddress((void**)&Wfp,  g_Wf);
    cudaGetSymbolAddress((void**)&bfp,  g_bf);
    cudaGetSymbolAddress((void**)&agg2, g_agg2);

    const int GSMEM = 2 * 128 * SA * 4;   // 69632 B
    cudaFuncSetAttribute(gemm_mma<true, 1, 1>,
                         cudaFuncAttributeMaxDynamicSharedMemorySize, GSMEM);
    cudaFuncSetAttribute(gemm_mma<false, 1, 0>,
                         cudaFuncAttributeMaxDynamicSharedMemorySize, GSMEM);

    const int B = 256;
    int gblk = (N + 127) / 128;
    int nwarp_blk = (N + 7) / 8;
    int scan_g = (N + SCAN_B - 1) / SCAN_B;

    // CSR build (+ xs convert in scan_add; cnt arrays re-zeroed in permute tail)
    k_count   <<<(E + B - 1) / B, B>>>(ei, E);
    k_scan_blk<<<scan_g, SCAN_B>>>(N);
    k_scan_add<<<scan_g, SCAN_B>>>(x, N, scan_g);
    k_permute <<<(E + B - 1) / B, B>>>(ei, E, N);
    // weight fold prep
    k_foldw   <<<129, 256>>>(W2, Wc1, b2, bc1);
    // conv1 (h1s = relu(conv)*dis stored fp16)
    k_gather1 <<<nwarp_blk, B>>>(N);
    gemm_mma<true, 1, 1> <<<dim3(gblk, 1), 256, GSMEM>>>(agg1, W1, b1, h1s, N, 64, 128);
    // conv2 (+ folded classifier layer 1)
    k_gather2 <<<nwarp_blk, B>>>(N);
    gemm_mma<false, 1, 0><<<dim3(gblk, 2), 256, GSMEM>>>(agg2, Wfp, bfp, ABh, N, 128, 256);
    // query
    k_query   <<<((long)Q * 32 + B - 1) / B, B>>>(eli, Wc2, bc2, out, Q);
}

// round 14
// speedup vs baseline: 1.3994x; 1.3994x over previous
#include <cuda_runtime.h>
#include <cuda_fp16.h>
#include <cstdint>

#define N_NODES 50000
#define E_MAX   850000
#define SCAN_B  1024

// ---------------- scratch (allocation-free: __device__ globals; zero-initialized at load) ----------------
__device__ __align__(128) int    g_cntr[N_NODES];
__device__ __align__(128) int    g_cntc[N_NODES];
__device__ __align__(128) int    g_rp  [N_NODES + 1];
__device__ __align__(128) int    g_fill[N_NODES];
__device__ __align__(128) int    g_bsum[64];
__device__ __align__(128) int    g_srt [E_MAX];
__device__ __align__(128) float  g_dis [N_NODES];
__device__ __align__(128) __half g_xs  [N_NODES * 64];    // fp16 x * dis[row]
__device__ __align__(128) float  g_agg1[N_NODES * 64];
__device__ __align__(128) __half g_h1s [N_NODES * 128];   // fp16 h1 * dis[row]
__device__ __align__(128) float  g_agg2[N_NODES * 128];
__device__ __align__(128) __half g_ABh [N_NODES * 256];   // fp16 [A | B] per node
__device__ __align__(128) float  g_Wf  [128 * 256];       // W2 @ [Wc1_top | Wc1_bot]
__device__ __align__(128) float  g_bf  [256];             // [b2@Wc1_top + bc1 | b2@Wc1_bot]

// ---------------- helpers ----------------
__device__ __forceinline__ uint32_t f2tf32(float f) {
    uint32_t r; asm("cvt.rna.tf32.f32 %0, %1;" : "=r"(r) : "f"(f)); return r;
}
__device__ __forceinline__ void mma_tf32(float* d, const uint32_t* a, uint32_t b0, uint32_t b1) {
    asm volatile(
        "mma.sync.aligned.m16n8k8.row.col.f32.tf32.tf32.f32 "
        "{%0,%1,%2,%3}, {%4,%5,%6,%7}, {%8,%9}, {%0,%1,%2,%3};"
        : "+f"(d[0]), "+f"(d[1]), "+f"(d[2]), "+f"(d[3])
        : "r"(a[0]), "r"(a[1]), "r"(a[2]), "r"(a[3]), "r"(b0), "r"(b1));
}

// ---------------- CSR build ----------------
__global__ void k_count(const int* __restrict__ ei, int E) {
    int e = blockIdx.x * blockDim.x + threadIdx.x;
    if (e >= E) return;
    atomicAdd(&g_cntr[__ldg(ei + e)], 1);
    atomicAdd(&g_cntc[__ldg(ei + E + e)], 1);
}
// phase 1: per-block exclusive scan of cntc; also dis = rsqrt(1+cntr)
__global__ __launch_bounds__(SCAN_B) void k_scan_blk(int n) {
    __shared__ int wsum[32];
    int tid = threadIdx.x, lane = tid & 31, wid = tid >> 5;
    int i = blockIdx.x * SCAN_B + tid;
    if (i < n) g_dis[i] = rsqrtf(1.0f + (float)g_cntr[i]);
    int v = (i < n) ? g_cntc[i] : 0;
    int s = v;
#pragma unroll
    for (int o = 1; o < 32; o <<= 1) {
        int t = __shfl_up_sync(0xffffffffu, s, o);
        if (lane >= o) s += t;
    }
    if (lane == 31) wsum[wid] = s;
    __syncthreads();
    if (wid == 0) {
        int ws = wsum[lane];
#pragma unroll
        for (int o = 1; o < 32; o <<= 1) {
            int t = __shfl_up_sync(0xffffffffu, ws, o);
            if (lane >= o) ws += t;
        }
        wsum[lane] = ws;
    }
    __syncthreads();
    int incl = s + (wid ? wsum[wid - 1] : 0);
    if (i < n) g_rp[i] = incl - v;
    if (tid == SCAN_B - 1) g_bsum[blockIdx.x] = incl;
}
// phase 2+3 merged: each block reduces its own offset from g_bsum, then adds.
__global__ __launch_bounds__(SCAN_B) void k_scan_add(int n, int nblk) {
    __shared__ int red[2];
    int b = blockIdx.x, tid = threadIdx.x;
    if (tid < 64) {
        int v = (tid < b) ? g_bsum[tid] : 0;
#pragma unroll
        for (int o = 16; o > 0; o >>= 1) v += __shfl_down_sync(0xffffffffu, v, o);
        if ((tid & 31) == 0) red[tid >> 5] = v;
    }
    __syncthreads();
    int off = red[0] + red[1];
    int i = b * SCAN_B + tid;
    if (i < n) {
        int v = g_rp[i] + off;
        g_rp[i] = v;
        g_fill[i] = v;
    }
    if (b == nblk - 1 && tid == 0) g_rp[n] = off + g_bsum[b];
}
// coalesced x -> xs = fp16(x * dis[row]); thread t handles float4 t
__global__ void k_xcvt(const float* __restrict__ x, int n16) {   // n16 = N*16 float4s
    int t = blockIdx.x * blockDim.x + threadIdx.x;
    if (t >= n16) return;
    float d = g_dis[t >> 4];
    float4 v = ((const float4*)x)[t];
    __half2 a = __floats2half2_rn(v.x * d, v.y * d);
    __half2 b = __floats2half2_rn(v.z * d, v.w * d);
    uint2 u;
    u.x = *(uint32_t*)&a;
    u.y = *(uint32_t*)&b;
    ((uint2*)g_xs)[t] = u;
}
// permute + re-zero cnt arrays for next graph replay (cntr/cntc fully consumed by k_scan_blk)
__global__ void k_permute(const int* __restrict__ ei, int E, int n) {
    int e = blockIdx.x * blockDim.x + threadIdx.x;
    if (e < E) {
        int r = __ldg(ei + e);
        int c = __ldg(ei + E + e);
        int pos = atomicAdd(&g_fill[c], 1);
        g_srt[pos] = r;
    }
    if (e < n) { g_cntr[e] = 0; g_cntc[e] = 0; }
}

// ---------------- gather convs (warp per node; rows pre-scaled, pure-add inner loop) ----------------
// agg1[i] = dis_i * (xs[i] + sum_e xs[src])
__global__ __launch_bounds__(256) void k_gather1(int n) {
    int node = blockIdx.x * 8 + (threadIdx.x >> 5);
    int lane = threadIdx.x & 31;
    if (node >= n) return;
    const __half2* xs2 = (const __half2*)g_xs;
    float2 acc = __half22float2(xs2[node * 32 + lane]);
    int e = g_rp[node], end = g_rp[node + 1];
    while (e < end) {
        int cnt = end - e;
        if (cnt > 32) cnt = 32;
        int idx = (lane < cnt) ? __ldg(g_srt + e + lane) : 0;
#pragma unroll 4
        for (int j = 0; j < cnt; j++) {
            int s = __shfl_sync(0xffffffffu, idx, j);
            float2 v = __half22float2(xs2[s * 32 + lane]);
            acc.x += v.x;
            acc.y += v.y;
        }
        e += cnt;
    }
    float di = g_dis[node];
    acc.x *= di; acc.y *= di;
    ((float2*)g_agg1)[node * 32 + lane] = acc;
}
// agg2[i] = dis_i * (h1s[i] + sum_e h1s[src])
__global__ __launch_bounds__(256) void k_gather2(int n) {
    int node = blockIdx.x * 8 + (threadIdx.x >> 5);
    int lane = threadIdx.x & 31;
    if (node >= n) return;
    const uint2* h2 = (const uint2*)g_h1s;
    uint2 us = h2[node * 32 + lane];
    float2 f0 = __half22float2(*(__half2*)&us.x);
    float2 f1 = __half22float2(*(__half2*)&us.y);
    float4 acc = make_float4(f0.x, f0.y, f1.x, f1.y);
    int e = g_rp[node], end = g_rp[node + 1];
    while (e < end) {
        int cnt = end - e;
        if (cnt > 32) cnt = 32;
        int idx = (lane < cnt) ? __ldg(g_srt + e + lane) : 0;
#pragma unroll 4
        for (int j = 0; j < cnt; j++) {
            int s = __shfl_sync(0xffffffffu, idx, j);
            uint2 u0 = h2[s * 32 + lane];
            float2 a0 = __half22float2(*(__half2*)&u0.x);
            float2 a1 = __half22float2(*(__half2*)&u0.y);
            acc.x += a0.x;
            acc.y += a0.y;
            acc.z += a1.x;
            acc.w += a1.y;
        }
        e += cnt;
    }
    float di = g_dis[node];
    acc.x *= di; acc.y *= di; acc.z *= di; acc.w *= di;
    ((float4*)g_agg2)[node * 32 + lane] = acc;
}

// ---------------- fold prep (weights + bias in one kernel) ----------------
__global__ void k_foldw(const float* __restrict__ W2, const float* __restrict__ Wc1,
                        const float* __restrict__ b2, const float* __restrict__ bc1) {
    if (blockIdx.x == 128) {
        int n = threadIdx.x;
        int which = n >> 7, nn = n & 127;
        const float* wc = Wc1 + (which * 128) * 128 + nn;
        float acc = 0.f;
#pragma unroll 8
        for (int j = 0; j < 128; j++) acc = fmaf(b2[j], __ldg(wc + j * 128), acc);
        g_bf[n] = acc + (which ? 0.f : bc1[nn]);
        return;
    }
    int idx = blockIdx.x * 256 + threadIdx.x;
    int k = idx >> 8, n = idx & 255;
    int which = n >> 7, nn = n & 127;
    const float* w2row = W2 + k * 128;
    const float* wc = Wc1 + (which * 128) * 128 + nn;
    float acc = 0.f;
#pragma unroll 8
    for (int j = 0; j < 128; j++) acc = fmaf(__ldg(w2row + j), __ldg(wc + j * 128), acc);
    g_Wf[idx] = acc;
}

// ---------------- tf32 mma.sync GEMM ----------------
// OUTH: fp16 output. DSCALE: multiply output rows by g_dis[row] (for h1s path).
#define SA 68
template <bool RELU, int OUTH, int DSCALE>
__global__ __launch_bounds__(256) void gemm_mma(
    const float* __restrict__ A, const float* __restrict__ W,
    const float* __restrict__ bias, void* __restrict__ Cv,
    int M, int K, int NC) {
    extern __shared__ uint32_t sm[];
    uint32_t* As = sm;              // 128*68
    uint32_t* Ws = sm + 128 * SA;   // 128*68
    int tid = threadIdx.x, wid = tid >> 5, lane = tid & 31;
    int row0 = blockIdx.x * 128, col0 = blockIdx.y * 128;
    int wm = (wid & 3) * 32, wn = (wid >> 2) * 64;
    int gid = lane >> 2, tig = lane & 3;

    float acc[2][8][4];
#pragma unroll
    for (int ma = 0; ma < 2; ma++)
#pragma unroll
        for (int na = 0; na < 8; na++)
#pragma unroll
            for (int q = 0; q < 4; q++) acc[ma][na][q] = 0.f;

    int lda4 = K >> 2;
    const float4* A4 = (const float4*)A;

    for (int kc = 0; kc < K; kc += 64) {
        for (int i = tid; i < 128 * 16; i += 256) {
            int r = i >> 4, kk = i & 15;
            float4 v = make_float4(0.f, 0.f, 0.f, 0.f);
            int gr = row0 + r;
            if (gr < M) v = A4[gr * lda4 + (kc >> 2) + kk];
            uint4 tv;
            tv.x = f2tf32(v.x); tv.y = f2tf32(v.y); tv.z = f2tf32(v.z); tv.w = f2tf32(v.w);
            *(uint4*)(As + r * SA + kk * 4) = tv;
        }
        for (int i = tid; i < 64 * 128; i += 256) {
            int k = i >> 7, n = i & 127;
            Ws[n * SA + k] = f2tf32(__ldg(W + (kc + k) * NC + col0 + n));
        }
        __syncthreads();

        const uint32_t* a0p = As + (wm + gid) * SA;
        const uint32_t* b0p = Ws + (wn + gid) * SA;
#pragma unroll
        for (int ks = 0; ks < 64; ks += 8) {
            uint32_t afr[2][4];
#pragma unroll
            for (int ma = 0; ma < 2; ma++) {
                const uint32_t* p = a0p + ma * 16 * SA + ks + tig;
                afr[ma][0] = p[0];
                afr[ma][1] = p[8 * SA];
                afr[ma][2] = p[4];
                afr[ma][3] = p[8 * SA + 4];
            }
#pragma unroll
            for (int na = 0; na < 8; na++) {
                const uint32_t* p = b0p + na * 8 * SA + ks + tig;
                uint32_t b0 = p[0], b1 = p[4];
                mma_tf32(acc[0][na], afr[0], b0, b1);
                mma_tf32(acc[1][na], afr[1], b0, b1);
            }
        }
        __syncthreads();
    }

#pragma unroll
    for (int ma = 0; ma < 2; ma++) {
        int r0 = row0 + wm + ma * 16 + gid;
        float d0 = 1.f, d1 = 1.f;
        if (DSCALE) {
            if (r0 < M)     d0 = g_dis[r0];
            if (r0 + 8 < M) d1 = g_dis[r0 + 8];
        }
#pragma unroll
        for (int na = 0; na < 8; na++) {
            int c = col0 + wn + na * 8 + 2 * tig;
            float bx = bias[c], by = bias[c + 1];
            float2 v0, v1;
            v0.x = acc[ma][na][0] + bx; v0.y = acc[ma][na][1] + by;
            v1.x = acc[ma][na][2] + bx; v1.y = acc[ma][na][3] + by;
            if (RELU) {
                v0.x = fmaxf(v0.x, 0.f); v0.y = fmaxf(v0.y, 0.f);
                v1.x = fmaxf(v1.x, 0.f); v1.y = fmaxf(v1.y, 0.f);
            }
            if (DSCALE) {
                v0.x *= d0; v0.y *= d0;
                v1.x *= d1; v1.y *= d1;
            }
            if (OUTH) {
                __half* C = (__half*)Cv;
                if (r0 < M)     *(__half2*)(C + (long)r0 * NC + c)       = __floats2half2_rn(v0.x, v0.y);
                if (r0 + 8 < M) *(__half2*)(C + (long)(r0 + 8) * NC + c) = __floats2half2_rn(v1.x, v1.y);
            } else {
                float* C = (float*)Cv;
                if (r0 < M)     *(float2*)(C + (long)r0 * NC + c)       = v0;
                if (r0 + 8 < M) *(float2*)(C + (long)(r0 + 8) * NC + c) = v1;
            }
        }
    }
}

// ---------------- query (fp16 AB reads) ----------------
__global__ void k_query(const int* __restrict__ eli, const float* __restrict__ Wc2,
                        const float* __restrict__ bc2, float* __restrict__ out, int Q) {
    int t = blockIdx.x * blockDim.x + threadIdx.x;
    int q = t >> 5, lane = t & 31;
    if (q >= Q) return;
    int s = __ldg(eli + q);
    int d = __ldg(eli + Q + q);
    const uint2* AB2 = (const uint2*)g_ABh;    // 4 halves per lane
    uint2 ua = AB2[s * 64 + lane];
    uint2 ub = AB2[d * 64 + 32 + lane];
    float2 a0 = __half22float2(*(__half2*)&ua.x);
    float2 a1 = __half22float2(*(__half2*)&ua.y);
    float2 b0 = __half22float2(*(__half2*)&ub.x);
    float2 b1 = __half22float2(*(__half2*)&ub.y);
    float4 w = ((const float4*)Wc2)[lane];
    float ux = fmaxf(a0.x + b0.x, 0.f);
    float uy = fmaxf(a0.y + b0.y, 0.f);
    float uz = fmaxf(a1.x + b1.x, 0.f);
    float uw = fmaxf(a1.y + b1.y, 0.f);
    float sum = ux * w.x + uy * w.y + uz * w.z + uw * w.w;
#pragma unroll
    for (int o = 16; o > 0; o >>= 1) sum += __shfl_xor_sync(0xffffffffu, sum, o);
    if (lane == 0) out[q] = sum + bc2[0];
}

extern "C" void kernel_launch(void* const* d_in, const int* in_sizes, int n_in,
                              void* d_out, int out_size) {
    const float* x   = (const float*)d_in[0];
    const int*   ei  = (const int*)  d_in[1];
    const int*   eli = (const int*)  d_in[2];
    const float* W1  = (const float*)d_in[3];
    const float* b1  = (const float*)d_in[4];
    const float* W2  = (const float*)d_in[5];
    const float* b2  = (const float*)d_in[6];
    const float* Wc1 = (const float*)d_in[7];
    const float* bc1 = (const float*)d_in[8];
    const float* Wc2 = (const float*)d_in[9];
    const float* bc2 = (const float*)d_in[10];
    float* out = (float*)d_out;

    int N = in_sizes[0] / 64;
    int E = in_sizes[1] / 2;
    int Q = in_sizes[2] / 2;

    float *agg1, *Wfp, *bfp, *agg2;
    __half *h1s, *ABh;
    cudaGetSymbolAddress((void**)&agg1, g_agg1);
    cudaGetSymbolAddress((void**)&h1s,  g_h1s);
    cudaGetSymbolAddress((void**)&ABh,  g_ABh);
    cudaGetSymbolAddress((void**)&Wfp,  g_Wf);
    cudaGetSymbolAddress((void**)&bfp,  g_bf);
    cudaGetSymbolAddress((void**)&agg2, g_agg2);

    const int GSMEM = 2 * 128 * SA * 4;   // 69632 B
    cudaFuncSetAttribute(gemm_mma<true, 1, 1>,
                         cudaFuncAttributeMaxDynamicSharedMemorySize, GSMEM);
    cudaFuncSetAttribute(gemm_mma<false, 1, 0>,
                         cudaFuncAttributeMaxDynamicSharedMemorySize, GSMEM);

    const int B = 256;
    int gblk = (N + 127) / 128;
    int nwarp_blk = (N + 7) / 8;
    int scan_g = (N + SCAN_B - 1) / SCAN_B;

    // CSR build (cnt arrays re-zeroed in permute tail; xcvt coalesced, after scan_blk for dis)
    k_count   <<<(E + B - 1) / B, B>>>(ei, E);
    k_scan_blk<<<scan_g, SCAN_B>>>(N);
    k_scan_add<<<scan_g, SCAN_B>>>(N, scan_g);
    k_xcvt    <<<(N * 16 + B - 1) / B, B>>>(x, N * 16);
    k_permute <<<(E + B - 1) / B, B>>>(ei, E, N);
    // weight fold prep
    k_foldw   <<<129, 256>>>(W2, Wc1, b2, bc1);
    // conv1 (h1s = relu(conv)*dis stored fp16)
    k_gather1 <<<nwarp_blk, B>>>(N);
    gemm_mma<true, 1, 1> <<<dim3(gblk, 1), 256, GSMEM>>>(agg1, W1, b1, h1s, N, 64, 128);
    // conv2 (+ folded classifier layer 1)
    k_gather2 <<<nwarp_blk, B>>>(N);
    gemm_mma<false, 1, 0><<<dim3(gblk, 2), 256, GSMEM>>>(agg2, Wfp, bfp, ABh, N, 128, 256);
    // query
    k_query   <<<((long)Q * 32 + B - 1) / B, B>>>(eli, Wc2, bc2, out, Q);
}

// round 15
// speedup vs baseline: 1.4502x; 1.0363x over previous
#include <cuda_runtime.h>
#include <cuda_fp16.h>
#include <cstdint>

#define N_NODES 50000
#define E_MAX   850000
#define SCAN_B  1024

// ---------------- scratch (allocation-free: __device__ globals; zero-initialized at load) ----------------
__device__ __align__(128) int    g_cntr[N_NODES];
__device__ __align__(128) int    g_cntc[N_NODES];
__device__ __align__(128) int    g_rp  [N_NODES + 1];
__device__ __align__(128) int    g_fill[N_NODES];
__device__ __align__(128) int    g_bsum[64];
__device__ __align__(128) int    g_srt [E_MAX];
__device__ __align__(128) float  g_dis [N_NODES];
__device__ __align__(128) __half g_xs  [N_NODES * 64];    // fp16 x * dis[row]
__device__ __align__(128) float  g_agg1[N_NODES * 64];
__device__ __align__(128) __half g_h1s [N_NODES * 128];   // fp16 h1 * dis[row]
__device__ __align__(128) float  g_agg2[N_NODES * 128];
__device__ __align__(128) __half g_ABh [N_NODES * 256];   // fp16 [A | B] per node
__device__ __align__(128) float  g_Wf  [128 * 256];       // W2 @ [Wc1_top | Wc1_bot]
__device__ __align__(128) float  g_bf  [256];             // [b2@Wc1_top + bc1 | b2@Wc1_bot]

// ---------------- helpers ----------------
__device__ __forceinline__ uint32_t f2tf32(float f) {
    uint32_t r; asm("cvt.rna.tf32.f32 %0, %1;" : "=r"(r) : "f"(f)); return r;
}
__device__ __forceinline__ void mma_tf32(float* d, const uint32_t* a, uint32_t b0, uint32_t b1) {
    asm volatile(
        "mma.sync.aligned.m16n8k8.row.col.f32.tf32.tf32.f32 "
        "{%0,%1,%2,%3}, {%4,%5,%6,%7}, {%8,%9}, {%0,%1,%2,%3};"
        : "+f"(d[0]), "+f"(d[1]), "+f"(d[2]), "+f"(d[3])
        : "r"(a[0]), "r"(a[1]), "r"(a[2]), "r"(a[3]), "r"(b0), "r"(b1));
}

// ---------------- merged: edge count (blocks [0, ecnt)) + weight fold (blocks [ecnt, ecnt+129)) ----------------
__global__ void k_count_fold(const int* __restrict__ ei, int E, int ecnt,
                             const float* __restrict__ W2, const float* __restrict__ Wc1,
                             const float* __restrict__ b2, const float* __restrict__ bc1) {
    int b = blockIdx.x;
    if (b < ecnt) {
        // original k_count body
        int e = b * 256 + threadIdx.x;
        if (e >= E) return;
        atomicAdd(&g_cntr[__ldg(ei + e)], 1);
        atomicAdd(&g_cntc[__ldg(ei + E + e)], 1);
        return;
    }
    int fb = b - ecnt;            // 0..128
    if (fb == 128) {
        // bias fold
        int n = threadIdx.x;
        int which = n >> 7, nn = n & 127;
        const float* wc = Wc1 + (which * 128) * 128 + nn;
        float acc = 0.f;
#pragma unroll 8
        for (int j = 0; j < 128; j++) acc = fmaf(b2[j], __ldg(wc + j * 128), acc);
        g_bf[n] = acc + (which ? 0.f : bc1[nn]);
        return;
    }
    // weight fold
    int idx = fb * 256 + threadIdx.x;
    int k = idx >> 8, n = idx & 255;
    int which = n >> 7, nn = n & 127;
    const float* w2row = W2 + k * 128;
    const float* wc = Wc1 + (which * 128) * 128 + nn;
    float acc = 0.f;
#pragma unroll 8
    for (int j = 0; j < 128; j++) acc = fmaf(__ldg(w2row + j), __ldg(wc + j * 128), acc);
    g_Wf[idx] = acc;
}

// ---------------- CSR scan phase 1: per-block exclusive scan of cntc; also dis = rsqrt(1+cntr) ----------------
__global__ __launch_bounds__(SCAN_B) void k_scan_blk(int n) {
    __shared__ int wsum[32];
    int tid = threadIdx.x, lane = tid & 31, wid = tid >> 5;
    int i = blockIdx.x * SCAN_B + tid;
    if (i < n) g_dis[i] = rsqrtf(1.0f + (float)g_cntr[i]);
    int v = (i < n) ? g_cntc[i] : 0;
    int s = v;
#pragma unroll
    for (int o = 1; o < 32; o <<= 1) {
        int t = __shfl_up_sync(0xffffffffu, s, o);
        if (lane >= o) s += t;
    }
    if (lane == 31) wsum[wid] = s;
    __syncthreads();
    if (wid == 0) {
        int ws = wsum[lane];
#pragma unroll
        for (int o = 1; o < 32; o <<= 1) {
            int t = __shfl_up_sync(0xffffffffu, ws, o);
            if (lane >= o) ws += t;
        }
        wsum[lane] = ws;
    }
    __syncthreads();
    int incl = s + (wid ? wsum[wid - 1] : 0);
    if (i < n) g_rp[i] = incl - v;
    if (tid == SCAN_B - 1) g_bsum[blockIdx.x] = incl;
}

// ---------------- merged: scan add (blocks [0, nblk)) + coalesced xcvt (blocks [nblk, nblk+xblk)) ----------------
__global__ __launch_bounds__(SCAN_B) void k_scan_add_xcvt(const float* __restrict__ x,
                                                          int n, int nblk, int n16) {
    int b = blockIdx.x, tid = threadIdx.x;
    if (b >= nblk) {
        // original coalesced k_xcvt body: thread t handles float4 t
        int t = (b - nblk) * SCAN_B + tid;
        if (t >= n16) return;
        float d = g_dis[t >> 4];
        float4 v = ((const float4*)x)[t];
        __half2 a = __floats2half2_rn(v.x * d, v.y * d);
        __half2 c = __floats2half2_rn(v.z * d, v.w * d);
        uint2 u;
        u.x = *(uint32_t*)&a;
        u.y = *(uint32_t*)&c;
        ((uint2*)g_xs)[t] = u;
        return;
    }
    __shared__ int red[2];
    if (tid < 64) {
        int v = (tid < b) ? g_bsum[tid] : 0;
#pragma unroll
        for (int o = 16; o > 0; o >>= 1) v += __shfl_down_sync(0xffffffffu, v, o);
        if ((tid & 31) == 0) red[tid >> 5] = v;
    }
    __syncthreads();
    int off = red[0] + red[1];
    int i = b * SCAN_B + tid;
    if (i < n) {
        int v = g_rp[i] + off;
        g_rp[i] = v;
        g_fill[i] = v;
    }
    if (b == nblk - 1 && tid == 0) g_rp[n] = off + g_bsum[b];
}

// permute + re-zero cnt arrays for next graph replay (cntr/cntc fully consumed by k_scan_blk)
__global__ void k_permute(const int* __restrict__ ei, int E, int n) {
    int e = blockIdx.x * blockDim.x + threadIdx.x;
    if (e < E) {
        int r = __ldg(ei + e);
        int c = __ldg(ei + E + e);
        int pos = atomicAdd(&g_fill[c], 1);
        g_srt[pos] = r;
    }
    if (e < n) { g_cntr[e] = 0; g_cntc[e] = 0; }
}

// ---------------- gather convs (warp per node; rows pre-scaled, pure-add inner loop) ----------------
// agg1[i] = dis_i * (xs[i] + sum_e xs[src])
__global__ __launch_bounds__(256) void k_gather1(int n) {
    int node = blockIdx.x * 8 + (threadIdx.x >> 5);
    int lane = threadIdx.x & 31;
    if (node >= n) return;
    const __half2* xs2 = (const __half2*)g_xs;
    float2 acc = __half22float2(xs2[node * 32 + lane]);
    int e = g_rp[node], end = g_rp[node + 1];
    while (e < end) {
        int cnt = end - e;
        if (cnt > 32) cnt = 32;
        int idx = (lane < cnt) ? __ldg(g_srt + e + lane) : 0;
#pragma unroll 4
        for (int j = 0; j < cnt; j++) {
            int s = __shfl_sync(0xffffffffu, idx, j);
            float2 v = __half22float2(xs2[s * 32 + lane]);
            acc.x += v.x;
            acc.y += v.y;
        }
        e += cnt;
    }
    float di = g_dis[node];
    acc.x *= di; acc.y *= di;
    ((float2*)g_agg1)[node * 32 + lane] = acc;
}
// agg2[i] = dis_i * (h1s[i] + sum_e h1s[src])
__global__ __launch_bounds__(256) void k_gather2(int n) {
    int node = blockIdx.x * 8 + (threadIdx.x >> 5);
    int lane = threadIdx.x & 31;
    if (node >= n) return;
    const uint2* h2 = (const uint2*)g_h1s;
    uint2 us = h2[node * 32 + lane];
    float2 f0 = __half22float2(*(__half2*)&us.x);
    float2 f1 = __half22float2(*(__half2*)&us.y);
    float4 acc = make_float4(f0.x, f0.y, f1.x, f1.y);
    int e = g_rp[node], end = g_rp[node + 1];
    while (e < end) {
        int cnt = end - e;
        if (cnt > 32) cnt = 32;
        int idx = (lane < cnt) ? __ldg(g_srt + e + lane) : 0;
#pragma unroll 4
        for (int j = 0; j < cnt; j++) {
            int s = __shfl_sync(0xffffffffu, idx, j);
            uint2 u0 = h2[s * 32 + lane];
            float2 a0 = __half22float2(*(__half2*)&u0.x);
            float2 a1 = __half22float2(*(__half2*)&u0.y);
            acc.x += a0.x;
            acc.y += a0.y;
            acc.z += a1.x;
            acc.w += a1.y;
        }
        e += cnt;
    }
    float di = g_dis[node];
    acc.x *= di; acc.y *= di; acc.z *= di; acc.w *= di;
    ((float4*)g_agg2)[node * 32 + lane] = acc;
}

// ---------------- tf32 mma.sync GEMM ----------------
// OUTH: fp16 output. DSCALE: multiply output rows by g_dis[row] (for h1s path).
#define SA 68
template <bool RELU, int OUTH, int DSCALE>
__global__ __launch_bounds__(256) void gemm_mma(
    const float* __restrict__ A, const float* __restrict__ W,
    const float* __restrict__ bias, void* __restrict__ Cv,
    int M, int K, int NC) {
    extern __shared__ uint32_t sm[];
    uint32_t* As = sm;              // 128*68
    uint32_t* Ws = sm + 128 * SA;   // 128*68
    int tid = threadIdx.x, wid = tid >> 5, lane = tid & 31;
    int row0 = blockIdx.x * 128, col0 = blockIdx.y * 128;
    int wm = (wid & 3) * 32, wn = (wid >> 2) * 64;
    int gid = lane >> 2, tig = lane & 3;

    float acc[2][8][4];
#pragma unroll
    for (int ma = 0; ma < 2; ma++)
#pragma unroll
        for (int na = 0; na < 8; na++)
#pragma unroll
            for (int q = 0; q < 4; q++) acc[ma][na][q] = 0.f;

    int lda4 = K >> 2;
    const float4* A4 = (const float4*)A;

    for (int kc = 0; kc < K; kc += 64) {
        for (int i = tid; i < 128 * 16; i += 256) {
            int r = i >> 4, kk = i & 15;
            float4 v = make_float4(0.f, 0.f, 0.f, 0.f);
            int gr = row0 + r;
            if (gr < M) v = A4[gr * lda4 + (kc >> 2) + kk];
            uint4 tv;
            tv.x = f2tf32(v.x); tv.y = f2tf32(v.y); tv.z = f2tf32(v.z); tv.w = f2tf32(v.w);
            *(uint4*)(As + r * SA + kk * 4) = tv;
        }
        for (int i = tid; i < 64 * 128; i += 256) {
            int k = i >> 7, n = i & 127;
            Ws[n * SA + k] = f2tf32(__ldg(W + (kc + k) * NC + col0 + n));
        }
        __syncthreads();

        const uint32_t* a0p = As + (wm + gid) * SA;
        const uint32_t* b0p = Ws + (wn + gid) * SA;
#pragma unroll
        for (int ks = 0; ks < 64; ks += 8) {
            uint32_t afr[2][4];
#pragma unroll
            for (int ma = 0; ma < 2; ma++) {
                const uint32_t* p = a0p + ma * 16 * SA + ks + tig;
                afr[ma][0] = p[0];
                afr[ma][1] = p[8 * SA];
                afr[ma][2] = p[4];
                afr[ma][3] = p[8 * SA + 4];
            }
#pragma unroll
            for (int na = 0; na < 8; na++) {
                const uint32_t* p = b0p + na * 8 * SA + ks + tig;
                uint32_t b0 = p[0], b1 = p[4];
                mma_tf32(acc[0][na], afr[0], b0, b1);
                mma_tf32(acc[1][na], afr[1], b0, b1);
            }
        }
        __syncthreads();
    }

#pragma unroll
    for (int ma = 0; ma < 2; ma++) {
        int r0 = row0 + wm + ma * 16 + gid;
        float d0 = 1.f, d1 = 1.f;
        if (DSCALE) {
            if (r0 < M)     d0 = g_dis[r0];
            if (r0 + 8 < M) d1 = g_dis[r0 + 8];
        }
#pragma unroll
        for (int na = 0; na < 8; na++) {
            int c = col0 + wn + na * 8 + 2 * tig;
            float bx = bias[c], by = bias[c + 1];
            float2 v0, v1;
            v0.x = acc[ma][na][0] + bx; v0.y = acc[ma][na][1] + by;
            v1.x = acc[ma][na][2] + bx; v1.y = acc[ma][na][3] + by;
            if (RELU) {
                v0.x = fmaxf(v0.x, 0.f); v0.y = fmaxf(v0.y, 0.f);
                v1.x = fmaxf(v1.x, 0.f); v1.y = fmaxf(v1.y, 0.f);
            }
            if (DSCALE) {
                v0.x *= d0; v0.y *= d0;
                v1.x *= d1; v1.y *= d1;
            }
            if (OUTH) {
                __half* C = (__half*)Cv;
                if (r0 < M)     *(__half2*)(C + (long)r0 * NC + c)       = __floats2half2_rn(v0.x, v0.y);
                if (r0 + 8 < M) *(__half2*)(C + (long)(r0 + 8) * NC + c) = __floats2half2_rn(v1.x, v1.y);
            } else {
                float* C = (float*)Cv;
                if (r0 < M)     *(float2*)(C + (long)r0 * NC + c)       = v0;
                if (r0 + 8 < M) *(float2*)(C + (long)(r0 + 8) * NC + c) = v1;
            }
        }
    }
}

// ---------------- query (fp16 AB reads) ----------------
__global__ void k_query(const int* __restrict__ eli, const float* __restrict__ Wc2,
                        const float* __restrict__ bc2, float* __restrict__ out, int Q) {
    int t = blockIdx.x * blockDim.x + threadIdx.x;
    int q = t >> 5, lane = t & 31;
    if (q >= Q) return;
    int s = __ldg(eli + q);
    int d = __ldg(eli + Q + q);
    const uint2* AB2 = (const uint2*)g_ABh;    // 4 halves per lane
    uint2 ua = AB2[s * 64 + lane];
    uint2 ub = AB2[d * 64 + 32 + lane];
    float2 a0 = __half22float2(*(__half2*)&ua.x);
    float2 a1 = __half22float2(*(__half2*)&ua.y);
    float2 b0 = __half22float2(*(__half2*)&ub.x);
    float2 b1 = __half22float2(*(__half2*)&ub.y);
    float4 w = ((const float4*)Wc2)[lane];
    float ux = fmaxf(a0.x + b0.x, 0.f);
    float uy = fmaxf(a0.y + b0.y, 0.f);
    float uz = fmaxf(a1.x + b1.x, 0.f);
    float uw = fmaxf(a1.y + b1.y, 0.f);
    float sum = ux * w.x + uy * w.y + uz * w.z + uw * w.w;
#pragma unroll
    for (int o = 16; o > 0; o >>= 1) sum += __shfl_xor_sync(0xffffffffu, sum, o);
    if (lane == 0) out[q] = sum + bc2[0];
}

extern "C" void kernel_launch(void* const* d_in, const int* in_sizes, int n_in,
                              void* d_out, int out_size) {
    const float* x   = (const float*)d_in[0];
    const int*   ei  = (const int*)  d_in[1];
    const int*   eli = (const int*)  d_in[2];
    const float* W1  = (const float*)d_in[3];
    const float* b1  = (const float*)d_in[4];
    const float* W2  = (const float*)d_in[5];
    const float* b2  = (const float*)d_in[6];
    const float* Wc1 = (const float*)d_in[7];
    const float* bc1 = (const float*)d_in[8];
    const float* Wc2 = (const float*)d_in[9];
    const float* bc2 = (const float*)d_in[10];
    float* out = (float*)d_out;

    int N = in_sizes[0] / 64;
    int E = in_sizes[1] / 2;
    int Q = in_sizes[2] / 2;

    float *agg1, *Wfp, *bfp, *agg2;
    __half *h1s, *ABh;
    cudaGetSymbolAddress((void**)&agg1, g_agg1);
    cudaGetSymbolAddress((void**)&h1s,  g_h1s);
    cudaGetSymbolAddress((void**)&ABh,  g_ABh);
    cudaGetSymbolAddress((void**)&Wfp,  g_Wf);
    cudaGetSymbolAddress((void**)&bfp,  g_bf);
    cudaGetSymbolAddress((void**)&agg2, g_agg2);

    const int GSMEM = 2 * 128 * SA * 4;   // 69632 B
    cudaFuncSetAttribute(gemm_mma<true, 1, 1>,
                         cudaFuncAttributeMaxDynamicSharedMemorySize, GSMEM);
    cudaFuncSetAttribute(gemm_mma<false, 1, 0>,
                         cudaFuncAttributeMaxDynamicSharedMemorySize, GSMEM);

    const int B = 256;
    int gblk = (N + 127) / 128;
    int nwarp_blk = (N + 7) / 8;
    int scan_g = (N + SCAN_B - 1) / SCAN_B;
    int ecnt   = (E + B - 1) / B;
    int n16    = N * 16;
    int xblk   = (n16 + SCAN_B - 1) / SCAN_B;

    // CSR build + weight fold (merged) ; xs convert merged into scan_add
    k_count_fold   <<<ecnt + 129, B>>>(ei, E, ecnt, W2, Wc1, b2, bc1);
    k_scan_blk     <<<scan_g, SCAN_B>>>(N);
    k_scan_add_xcvt<<<scan_g + xblk, SCAN_B>>>(x, N, scan_g, n16);
    k_permute      <<<ecnt, B>>>(ei, E, N);
    // conv1 (h1s = relu(conv)*dis stored fp16)
    k_gather1 <<<nwarp_blk, B>>>(N);
    gemm_mma<true, 1, 1> <<<dim3(gblk, 1), 256, GSMEM>>>(agg1, W1, b1, h1s, N, 64, 128);
    // conv2 (+ folded classifier layer 1)
    k_gather2 <<<nwarp_blk, B>>>(N);
    gemm_mma<false, 1, 0><<<dim3(gblk, 2), 256, GSMEM>>>(agg2, Wfp, bfp, ABh, N, 128, 256);
    // query
    k_query   <<<((long)Q * 32 + B - 1) / B, B>>>(eli, Wc2, bc2, out, Q);
}